// round 1
// baseline (speedup 1.0000x reference)
#include <cuda_runtime.h>
#include <cuda_bf16.h>

#define TT 256
#define NMAX 8192
#define SIGMA_INV (1.0f / 100.0f)

// Scratch (allocation-free rule: device globals)
__device__ double gS[TT];      // S[t] = sum_j ev_j [y_j > t] exp(F1[j,t]/sigma)
__device__ float  gA[NMAX];    // A[i] = F1[i, y[i]]
__device__ double gL1;
__device__ double gL2;
__device__ int    gIs64;       // y stored as int64?

// ---------------------------------------------------------------------------
// Kernel 0: zero accumulators + detect y element width.
// int64 little-endian layout: first N int32 words = [v0,0,v1,0,...] (odd all 0,
// since 0 <= y < 256). int32 layout: odd slots are random y values in [0,256),
// cannot all be zero for N=8192 random draws.
// ---------------------------------------------------------------------------
__global__ void surv_init_kernel(const int* __restrict__ y32, int N) {
    int t = threadIdx.x;
    if (t < TT) gS[t] = 0.0;
    if (t == 0) { gL1 = 0.0; gL2 = 0.0; }

    int orv = 0;
    for (int i = 2 * t + 1; i < N; i += 2 * blockDim.x) orv |= y32[i];

    __shared__ int sor;
    if (t == 0) sor = 0;
    __syncthreads();
    if (orv) atomicOr(&sor, 1);
    __syncthreads();
    if (t == 0) gIs64 = (sor == 0) ? 1 : 0;
}

// ---------------------------------------------------------------------------
// Kernel 1: per-row cumsum (block scan, 256 threads = T), L1 contribution,
// S[t] partials (held per-thread across rows, single atomic at end), A[i].
// ---------------------------------------------------------------------------
__global__ void __launch_bounds__(TT)
surv_row_kernel(const float* __restrict__ yp,
                const void*  __restrict__ yv,
                const float* __restrict__ status,
                int N) {
    __shared__ float  sWarp[8];
    __shared__ float  sA, sP;

    const int t    = threadIdx.x;
    const int lane = t & 31;
    const int w    = t >> 5;
    const int is64 = gIs64;

    double accS  = 0.0;   // this thread owns column t of S
    double accL1 = 0.0;   // only thread 0 uses it

    for (int j = blockIdx.x; j < N; j += gridDim.x) {
        const float v = yp[(size_t)j * TT + t];

        // inclusive scan over 256 elements: warp scan + warp-sum scan
        float x = v;
        #pragma unroll
        for (int o = 1; o < 32; o <<= 1) {
            float n = __shfl_up_sync(0xffffffffu, x, o);
            if (lane >= o) x += n;
        }
        if (lane == 31) sWarp[w] = x;
        __syncthreads();
        if (w == 0 && lane < 8) {
            float s = sWarp[lane];
            #pragma unroll
            for (int o = 1; o < 8; o <<= 1) {
                float n = __shfl_up_sync(0xffu, s, o);
                if (lane >= o) s += n;
            }
            sWarp[lane] = s;
        }
        __syncthreads();
        const float F = x + ((w > 0) ? sWarp[w - 1] : 0.0f);  // F1[j, t]

        const int yj = is64 ? (int)((const long long*)yv)[j]
                            : ((const int*)yv)[j];
        const float st = status[j];
        const bool  ev = (st > 0.5f);

        if (t == yj) { sA = F; sP = v; }
        __syncthreads();
        const float A = sA;

        if (t == 0) {
            const float p = sP;
            accL1 += -(double)(st * logf(p))
                     -(double)((1.0f - st) * logf(1.0f - A));
            gA[j] = A;
        }
        if (ev && t < yj) {
            accS += (double)__expf(F * SIGMA_INV);
        }
        __syncthreads();  // protect sWarp/sA/sP for next row
    }

    atomicAdd(&gS[t], accS);
    if (t == 0) atomicAdd(&gL1, accL1);
}

// ---------------------------------------------------------------------------
// Kernel 2: L2 = sum_i ev_i * exp(-A_i/sigma) * S[y_i]
// ---------------------------------------------------------------------------
__global__ void __launch_bounds__(256)
surv_pair_kernel(const void* __restrict__ yv,
                 const float* __restrict__ status,
                 int N) {
    const int is64 = gIs64;
    double acc = 0.0;
    for (int i = blockIdx.x * blockDim.x + threadIdx.x; i < N;
         i += gridDim.x * blockDim.x) {
        const float st = status[i];
        if (st > 0.5f) {
            const int yi = is64 ? (int)((const long long*)yv)[i]
                                : ((const int*)yv)[i];
            acc += (double)__expf(-gA[i] * SIGMA_INV) * gS[yi];
        }
    }
    // block reduce (double)
    #pragma unroll
    for (int o = 16; o > 0; o >>= 1)
        acc += __shfl_down_sync(0xffffffffu, acc, o);
    __shared__ double sRed[8];
    const int lane = threadIdx.x & 31, w = threadIdx.x >> 5;
    if (lane == 0) sRed[w] = acc;
    __syncthreads();
    if (w == 0) {
        double a = (lane < 8) ? sRed[lane] : 0.0;
        #pragma unroll
        for (int o = 4; o > 0; o >>= 1)
            a += __shfl_down_sync(0xffu, a, o);
        if (lane == 0) atomicAdd(&gL2, a);
    }
}

// ---------------------------------------------------------------------------
// Kernel 3: finalize
// ---------------------------------------------------------------------------
__global__ void surv_final_kernel(float* __restrict__ out) {
    out[0] = (float)(gL1 + gL2);
}

extern "C" void kernel_launch(void* const* d_in, const int* in_sizes, int n_in,
                              void* d_out, int out_size) {
    const float* y_pred = (const float*)d_in[0];
    const void*  y      = d_in[1];
    const float* status = (const float*)d_in[2];
    float* out = (float*)d_out;

    const int N = in_sizes[2];  // status has N elements regardless of y width

    surv_init_kernel<<<1, 256>>>((const int*)y, N);
    surv_row_kernel<<<512, TT>>>(y_pred, y, status, N);
    surv_pair_kernel<<<32, 256>>>(y, status, N);
    surv_final_kernel<<<1, 1>>>(out);
}

// round 2
// speedup vs baseline: 1.9607x; 1.9607x over previous
#include <cuda_runtime.h>
#include <cuda_bf16.h>

#define TT 256
#define NMAX 8192
#define SIGMA_INV (1.0f / 100.0f)
#define BLOCKS 304            // 2 per SM on GB300 (152 SMs)
#define THREADS 256
#define WPB 8                 // warps per block

// Scratch: device globals (allocation-free rule). Zero-initialized at module
// load; the LAST block of every launch re-zeros them after consuming, so the
// kernel is replay-deterministic under graph capture.
__device__ float        gS[TT];     // S[t] = sum_j ev_j [y_j > t] exp(F1[j,t]/s)
__device__ float        gE[NMAX];   // ev_i * exp(-A_i / sigma)
__device__ double       gL1;
__device__ unsigned int gCount;

// exp(x) for |x| <= 0.009 : cubic Taylor, rel err < 3e-10
__device__ __forceinline__ float exp_small(float x) {
    return fmaf(x, fmaf(x, fmaf(x, 0.16666667f, 0.5f), 1.0f), 1.0f);
}

__global__ void __launch_bounds__(THREADS)
surv_fused(const float* __restrict__ yp,
           const void*  __restrict__ yv,
           const float* __restrict__ status,
           int N,
           float* __restrict__ out) {
    const int t    = threadIdx.x;
    const int lane = t & 31;
    const int w    = t >> 5;

    // ---- detect y element width (int64 little-endian: odd 32-bit words all 0)
    __shared__ int sor;
    if (t == 0) sor = 0;
    __syncthreads();
    {
        const int* y32 = (const int*)yv;
        int idx = 2 * t + 1;
        int v = (idx < N) ? y32[idx] : 0;   // words 1..511 (cached in L2)
        unsigned b = __ballot_sync(0xffffffffu, v != 0);
        if (lane == 0 && b) atomicOr(&sor, 1);
    }
    __syncthreads();
    const bool is64 = (sor == 0);

    // ---- Phase A: warp-per-row scan, no block syncs in the loop ----
    const int gw = blockIdx.x * WPB + w;
    const int GW = gridDim.x * WPB;

    float acc[8];
    #pragma unroll
    for (int k = 0; k < 8; k++) acc[k] = 0.0f;
    float accL1 = 0.0f;

    for (int j = gw; j < N; j += GW) {
        const float* row = yp + (size_t)j * TT + lane * 8;
        const float4 a0 = *(const float4*)(row);
        const float4 a1 = *(const float4*)(row + 4);
        float v[8] = {a0.x, a0.y, a0.z, a0.w, a1.x, a1.y, a1.z, a1.w};

        // local inclusive prefix of 8
        float s[8];
        s[0] = v[0];
        #pragma unroll
        for (int k = 1; k < 8; k++) s[k] = s[k - 1] + v[k];

        // warp exclusive scan of lane totals
        float tot = s[7];
        float sc = tot;
        #pragma unroll
        for (int o = 1; o < 32; o <<= 1) {
            float n = __shfl_up_sync(0xffffffffu, sc, o);
            if (lane >= o) sc += n;
        }
        const float off = sc - tot;            // exclusive offset for this lane

        // row metadata (lane 0 loads, broadcast)
        int yj = 0; float st = 0.0f;
        if (lane == 0) {
            yj = is64 ? (int)((const long long*)yv)[j] : ((const int*)yv)[j];
            st = status[j];
        }
        yj = __shfl_sync(0xffffffffu, yj, 0);
        st = __shfl_sync(0xffffffffu, st, 0);

        // extract A = F1[j, yj], p = y_pred[j, yj]
        const int srcLane = yj >> 3, srcIdx = yj & 7;
        float fa = 0.0f, va = 0.0f;
        #pragma unroll
        for (int k = 0; k < 8; k++)
            if (k == srcIdx) { fa = off + s[k]; va = v[k]; }
        const float A = __shfl_sync(0xffffffffu, fa, srcLane);
        const float p = __shfl_sync(0xffffffffu, va, srcLane);

        const bool ev = (st > 0.5f);
        if (lane == 0) {
            accL1 += -(st * __logf(p)) - (1.0f - st) * __logf(1.0f - A);
            gE[j] = ev ? exp_small(-A * SIGMA_INV) : 0.0f;
        }
        if (ev) {                              // warp-uniform branch
            const int base = lane * 8;
            #pragma unroll
            for (int k = 0; k < 8; k++) {
                float e = exp_small((off + s[k]) * SIGMA_INV);
                if (base + k < yj) acc[k] += e;
            }
        }
    }

    if (lane == 0) atomicAdd(&gL1, (double)accL1);

    // block-level reduce of acc into gS (one float atomic per column per block)
    __shared__ float sRed[WPB][TT];
    #pragma unroll
    for (int k = 0; k < 8; k++) sRed[w][lane * 8 + k] = acc[k];
    __syncthreads();
    {
        float colSum = 0.0f;
        #pragma unroll
        for (int ww = 0; ww < WPB; ww++) colSum += sRed[ww][t];
        if (colSum != 0.0f) atomicAdd(&gS[t], colSum);
    }

    // ---- arrival counter: last block does Phase B + reset ----
    __threadfence();
    __shared__ bool isLast;
    if (t == 0) {
        unsigned old = atomicAdd(&gCount, 1u);
        isLast = (old == (unsigned)(gridDim.x - 1));
    }
    __syncthreads();
    if (!isLast) return;

    // Phase B: L2 = sum_i gE[i] * gS[y_i]
    float l2 = 0.0f;
    for (int i = t; i < N; i += THREADS) {
        float e = gE[i];
        if (e != 0.0f) {
            int yi = is64 ? (int)((const long long*)yv)[i] : ((const int*)yv)[i];
            l2 += e * gS[yi];
        }
    }
    // block reduce (double)
    double d = (double)l2;
    #pragma unroll
    for (int o = 16; o > 0; o >>= 1)
        d += __shfl_down_sync(0xffffffffu, d, o);
    __shared__ double sD[WPB];
    if (lane == 0) sD[w] = d;
    __syncthreads();
    if (t == 0) {
        double tot = 0.0;
        #pragma unroll
        for (int ww = 0; ww < WPB; ww++) tot += sD[ww];
        out[0] = (float)(gL1 + tot);
    }

    // reset for next replay (all consumers above are done in this block)
    __syncthreads();
    gS[t] = 0.0f;
    if (t == 0) { gL1 = 0.0; gCount = 0u; }
}

extern "C" void kernel_launch(void* const* d_in, const int* in_sizes, int n_in,
                              void* d_out, int out_size) {
    const float* y_pred = (const float*)d_in[0];
    const void*  y      = d_in[1];
    const float* status = (const float*)d_in[2];
    const int N = in_sizes[2];   // status length = N independent of y width
    surv_fused<<<BLOCKS, THREADS>>>(y_pred, y, status, N, (float*)d_out);
}